// round 6
// baseline (speedup 1.0000x reference)
#include <cuda_runtime.h>
#include <math.h>

// Greedy-collapse of the degenerate beam search (prob stays all-ones, beams
// never diverge, tie-break picks beam 0): one persistent kernel, 12 sequential
// steps of GRU -> logits -> softmax/argmax -> write, with hand-rolled grid
// barriers. All cross-CTA globals read via __ldcg (L1 not coherent across SMs).

#define NCTA  148
#define TPB   512
#define NWARP 16
#define VOCAB 16000
#define EDIM  256
#define HDIM  512
#define BATCH 8
#define PAD_ID 0
#define SOS_ID 1
#define EOS_ID 2

__device__ float    g_h[2][BATCH * HDIM];
__device__ float4   g_part[2][NCTA][BATCH];   // x=max, y=sumexp(local max), z=argmax idx (int bits)
__device__ unsigned g_bar;

__global__ void decoder_init(const float* __restrict__ hidden) {
    int t = blockIdx.x * blockDim.x + threadIdx.x;
    if (t < BATCH * HDIM) g_h[0][t] = hidden[t];   // h0 = hidden[0] (1,B,H) contiguous
    if (t == 0) g_bar = 0u;
}

__device__ __forceinline__ void grid_sync(unsigned target) {
    __syncthreads();
    if (threadIdx.x == 0) {
        __threadfence();
        atomicAdd(&g_bar, 1u);
        while (*((volatile unsigned*)&g_bar) < target) { __nanosleep(32); }
        __threadfence();
    }
    __syncthreads();
}

__global__ void __launch_bounds__(TPB, 1) decoder_main(
    const float* __restrict__ embedding,
    const float* __restrict__ w_ih,
    const float* __restrict__ w_hh,
    const float* __restrict__ b_ih,
    const float* __restrict__ b_hh,
    const float* __restrict__ w_out,
    const float* __restrict__ b_out,
    float* __restrict__ out,
    int lenseq)
{
    __shared__ float s_h[BATCH][HDIM];          // 16 KB  h_new staging
    __shared__ float s_log[NWARP][7][BATCH];    // 3.5 KB per-CTA logits
    __shared__ float s_M[BATCH], s_S[BATCH];
    __shared__ int   s_tok[BATCH], s_done[BATCH];

    const int tid  = threadIdx.x;
    const int wp   = tid >> 5;
    const int lane = tid & 31;
    const int cta  = blockIdx.x;
    // contiguous vocab chunk per CTA: first 16 CTAs get 109 rows, rest 108
    const int base  = cta * 108 + (cta < 16 ? cta : 16);
    const int nrows = 108 + (cta < 16 ? 1 : 0);

    if (tid < BATCH) s_tok[tid] = SOS_ID;
    __syncthreads();

    unsigned bar_target = 0;
    int cur = 0;

    for (int step = 0; step < lenseq; ++step) {
        const int nxt = cur ^ 1;

        // ================= Phase A: GRU cell (one warp per (b, j) pair) ======
        for (int t = cta * NWARP + wp; t < BATCH * HDIM; t += NCTA * NWARP) {
            const int b = t >> 9;            // /HDIM
            const int j = t & (HDIM - 1);
            const int tok = s_tok[b];
            const float hold = __ldcg(&g_h[cur][b * HDIM + j]);
            float hv;
            if (tok == PAD_ID || tok == EOS_ID) {
                hv = hold;                   // frozen state for done batch
            } else {
                const float4* e4  = (const float4*)(embedding + (size_t)tok * EDIM);
                const float4* wir = (const float4*)(w_ih + (size_t)j * EDIM);
                const float4* wiz = (const float4*)(w_ih + (size_t)(j + HDIM) * EDIM);
                const float4* win = (const float4*)(w_ih + (size_t)(j + 2 * HDIM) * EDIM);
                float ir = 0.f, iz = 0.f, in_ = 0.f;
                #pragma unroll
                for (int q = 0; q < 2; q++) {
                    const int c = q * 32 + lane;
                    float4 e = e4[c];
                    float4 a = wir[c]; ir  += e.x*a.x + e.y*a.y + e.z*a.z + e.w*a.w;
                    float4 z = wiz[c]; iz  += e.x*z.x + e.y*z.y + e.z*z.z + e.w*z.w;
                    float4 n = win[c]; in_ += e.x*n.x + e.y*n.y + e.z*n.z + e.w*n.w;
                }
                const float4* hp  = (const float4*)(g_h[cur] + b * HDIM);
                const float4* whr = (const float4*)(w_hh + (size_t)j * HDIM);
                const float4* whz = (const float4*)(w_hh + (size_t)(j + HDIM) * HDIM);
                const float4* whn = (const float4*)(w_hh + (size_t)(j + 2 * HDIM) * HDIM);
                float hr = 0.f, hz = 0.f, hn = 0.f;
                #pragma unroll
                for (int q = 0; q < 4; q++) {
                    const int c = q * 32 + lane;
                    float4 h = __ldcg(hp + c);
                    float4 a = whr[c]; hr += h.x*a.x + h.y*a.y + h.z*a.z + h.w*a.w;
                    float4 z = whz[c]; hz += h.x*z.x + h.y*z.y + h.z*z.z + h.w*z.w;
                    float4 n = whn[c]; hn += h.x*n.x + h.y*n.y + h.z*n.z + h.w*n.w;
                }
                #pragma unroll
                for (int off = 16; off; off >>= 1) {
                    ir  += __shfl_xor_sync(0xffffffffu, ir,  off);
                    iz  += __shfl_xor_sync(0xffffffffu, iz,  off);
                    in_ += __shfl_xor_sync(0xffffffffu, in_, off);
                    hr  += __shfl_xor_sync(0xffffffffu, hr,  off);
                    hz  += __shfl_xor_sync(0xffffffffu, hz,  off);
                    hn  += __shfl_xor_sync(0xffffffffu, hn,  off);
                }
                const float rg = 1.f / (1.f + expf(-(ir + b_ih[j]          + hr + b_hh[j])));
                const float zg = 1.f / (1.f + expf(-(iz + b_ih[j + HDIM]   + hz + b_hh[j + HDIM])));
                const float ng = tanhf(in_ + b_ih[j + 2 * HDIM] + rg * (hn + b_hh[j + 2 * HDIM]));
                hv = (1.f - zg) * ng + zg * hold;
            }
            if (lane == 0) g_h[nxt][b * HDIM + j] = hv;
        }
        bar_target += NCTA; grid_sync(bar_target);

        // ================= Phase B1: logits + per-CTA max/sumexp/argmax ======
        {
            const float4* src = (const float4*)g_h[nxt];
            for (int t = tid; t < BATCH * HDIM / 4; t += TPB)
                ((float4*)s_h)[t] = __ldcg(src + t);
        }
        __syncthreads();

        for (int r = wp; r < nrows; r += NWARP) {    // warp per vocab row
            const int row = base + r;
            const float4* wr = (const float4*)(w_out + (size_t)row * HDIM);
            float acc[BATCH];
            #pragma unroll
            for (int b = 0; b < BATCH; b++) acc[b] = 0.f;
            #pragma unroll
            for (int q = 0; q < 4; q++) {
                const int c = q * 32 + lane;
                float4 w4 = wr[c];
                #pragma unroll
                for (int b = 0; b < BATCH; b++) {
                    float4 h4 = ((const float4*)(s_h[b]))[c];
                    acc[b] = fmaf(w4.x, h4.x, fmaf(w4.y, h4.y,
                             fmaf(w4.z, h4.z, fmaf(w4.w, h4.w, acc[b]))));
                }
            }
            #pragma unroll
            for (int off = 16; off; off >>= 1)
                #pragma unroll
                for (int b = 0; b < BATCH; b++)
                    acc[b] += __shfl_xor_sync(0xffffffffu, acc[b], off);
            if (lane == 0) {
                const float bo = b_out[row];
                #pragma unroll
                for (int b = 0; b < BATCH; b++)
                    s_log[wp][r >> 4][b] = acc[b] + bo;
            }
        }
        __syncthreads();

        const int p = step & 1;
        if (wp < BATCH) {                       // warp b reduces batch b over CTA rows
            const int b = wp;
            float m = -INFINITY; int mi = 0x7fffffff;
            for (int r = lane; r < nrows; r += 32) {
                const float v = s_log[r & 15][r >> 4][b];
                if (v > m) { m = v; mi = base + r; }
            }
            #pragma unroll
            for (int off = 16; off; off >>= 1) {
                const float om = __shfl_xor_sync(0xffffffffu, m, off);
                const int   oi = __shfl_xor_sync(0xffffffffu, mi, off);
                if (om > m || (om == m && oi < mi)) { m = om; mi = oi; }
            }
            float s = 0.f;
            for (int r = lane; r < nrows; r += 32)
                s += __expf(s_log[r & 15][r >> 4][b] - m);
            #pragma unroll
            for (int off = 16; off; off >>= 1)
                s += __shfl_xor_sync(0xffffffffu, s, off);
            if (lane == 0)
                g_part[p][cta][b] = make_float4(m, s, __int_as_float(mi), 0.f);
        }
        bar_target += NCTA; grid_sync(bar_target);

        // ================= Phase B2: global reduce (redundant per CTA) + write
        if (wp < BATCH) {
            const int b = wp;
            float m = -INFINITY; int mi = 0x7fffffff;
            for (int c = lane; c < NCTA; c += 32) {
                const float4 pr = __ldcg(&g_part[p][c][b]);
                const int oi = __float_as_int(pr.z);
                if (pr.x > m || (pr.x == m && oi < mi)) { m = pr.x; mi = oi; }
            }
            #pragma unroll
            for (int off = 16; off; off >>= 1) {
                const float om = __shfl_xor_sync(0xffffffffu, m, off);
                const int   oi = __shfl_xor_sync(0xffffffffu, mi, off);
                if (om > m || (om == m && oi < mi)) { m = om; mi = oi; }
            }
            float S = 0.f;
            for (int c = lane; c < NCTA; c += 32) {
                const float4 pr = __ldcg(&g_part[p][c][b]);
                S += pr.y * __expf(pr.x - m);
            }
            #pragma unroll
            for (int off = 16; off; off >>= 1)
                S += __shfl_xor_sync(0xffffffffu, S, off);
            if (lane == 0) {
                const int oldtok = s_tok[b];
                const int d = (oldtok == PAD_ID) || (oldtok == EOS_ID);
                s_done[b] = d;
                s_M[b] = m; s_S[b] = S;
                s_tok[b] = d ? PAD_ID : mi;     // done -> PAD forever
            }
        }
        __syncthreads();

        float* ostep = out + (size_t)step * BATCH * VOCAB;
        for (int b = 0; b < BATCH; b++) {
            const float M   = s_M[b];
            const float inv = 1.0f / s_S[b];
            float* o = ostep + (size_t)b * VOCAB + base;
            if (s_done[b]) {
                for (int r = tid; r < nrows; r += TPB)
                    o[r] = (base + r == PAD_ID) ? 1.0f : 0.0f;   // pad one-hot
            } else {
                for (int r = tid; r < nrows; r += TPB)
                    o[r] = __expf(s_log[r & 15][r >> 4][b] - M) * inv;
            }
        }
        cur = nxt;
    }
}

extern "C" void kernel_launch(void* const* d_in, const int* in_sizes, int n_in,
                              void* d_out, int out_size) {
    const float* hidden    = (const float*)d_in[0];
    const float* embedding = (const float*)d_in[1];
    const float* w_ih      = (const float*)d_in[2];
    const float* w_hh      = (const float*)d_in[3];
    const float* b_ih      = (const float*)d_in[4];
    const float* b_hh      = (const float*)d_in[5];
    const float* w_out     = (const float*)d_in[6];
    const float* b_out     = (const float*)d_in[7];
    float* out = (float*)d_out;
    (void)in_sizes; (void)n_in;

    const int lenseq = out_size / (BATCH * VOCAB);   // host can't read device scalar
    if (lenseq <= 0) return;

    decoder_init<<<16, 256>>>(hidden);
    decoder_main<<<NCTA, TPB>>>(embedding, w_ih, w_hh, b_ih, b_hh,
                                w_out, b_out, out, lenseq);
}